// round 7
// baseline (speedup 1.0000x reference)
#include <cuda_runtime.h>
#include <cuda_fp16.h>
#include <cstdint>

// Problem constants (fixed shapes from the reference)
#define NE      513              // NUM_EDGES + 1
#define LHOPS   5
#define HEADS   8
#define FEAT    64
#define NPAIRS  (8*128*128)      // 131072
#define TBL     (LHOPS*NE*HEADS) // 20520 halves = 41040 B
#define TBL_BYTES (TBL*2)
#define GRID    148
#define CHUNK   886              // ceil(NPAIRS / 148)

// Precomputed projection table proj[l][e][h] in fp16
__device__ __align__(16) __half g_proj[TBL];

__device__ __forceinline__ uint32_t smem_u32(const void* p) {
    return (uint32_t)__cvta_generic_to_shared(p);
}

// Kernel A: proj[l][e][h] = sum_f edge_emb[e][f] * attn_w[l][f][h]
// grid=(17 e-tiles, 5 l), block=256 = 32e x 8h. emb tile AND w staged in smem;
// inner loop is all-smem, conflict-free (broadcast reads), float4 vectorized.
__global__ void proj_kernel(const float* __restrict__ emb,
                            const float* __restrict__ w) {
    __shared__ __align__(16) float s_emb[32 * FEAT];   // 8 KB
    __shared__ __align__(16) float s_w[FEAT * HEADS];  // 2 KB
    const int l   = blockIdx.y;
    const int tid = threadIdx.x;
    const int e0  = blockIdx.x * 32;

    // stage w[l] (128 float4)
    for (int i = tid; i < FEAT * HEADS / 4; i += 256)
        ((float4*)s_w)[i] = ((const float4*)(w + l * FEAT * HEADS))[i];
    // stage emb tile (512 float4, 2 per thread), zero-pad past NE
    #pragma unroll
    for (int r = 0; r < 2; ++r) {
        int i = tid + r * 256;              // float4 index
        int e = e0 + (i >> 4);
        ((float4*)s_emb)[i] = (e < NE)
            ? ((const float4*)(emb + (size_t)e * FEAT))[i & 15]
            : make_float4(0.f, 0.f, 0.f, 0.f);
    }
    __syncthreads();

    const int er = tid >> 3;                // 0..31 local e row
    const int h  = tid & 7;
    const int e  = e0 + er;
    if (e < NE) {
        float acc = 0.f;
        #pragma unroll
        for (int f4 = 0; f4 < 16; ++f4) {
            float4 ev = *(const float4*)(s_emb + er * FEAT + f4 * 4);
            acc = fmaf(ev.x, s_w[(f4 * 4 + 0) * HEADS + h], acc);
            acc = fmaf(ev.y, s_w[(f4 * 4 + 1) * HEADS + h], acc);
            acc = fmaf(ev.z, s_w[(f4 * 4 + 2) * HEADS + h], acc);
            acc = fmaf(ev.w, s_w[(f4 * 4 + 3) * HEADS + h], acc);
        }
        g_proj[(l * NE + e) * HEADS + h] = __float2half(acc);  // 64B/warp STG
    }
#if __CUDA_ARCH__ >= 900
    cudaTriggerProgrammaticLaunchCompletion();
#endif
}

// Kernel B: 148 CTAs (1/SM) x 1024 threads, PDL secondary.
// Phase 0 (overlaps proj): pd+dist -> registers.
// Phase 1 (after griddepsync): ONE cp.async.bulk stages the 41 KB fp16 table.
// Phase 2: gather — one LDS.128 per (pair,hop), HADD2 pairwise, fp32 accum.
__global__ void __launch_bounds__(1024, 1)
enc_kernel(const void* __restrict__ distp,
           const void* __restrict__ pdp,
           float* __restrict__ out) {
    __shared__ __align__(16) __half s_tbl[TBL];          // 41040 B
    __shared__ __align__(8) unsigned long long s_mbar;

    const int tid  = threadIdx.x;
    const int pair = blockIdx.x * CHUNK + tid;
    const bool act = (tid < CHUNK) && (pair < NPAIRS);
    const int p    = act ? pair : blockIdx.x * CHUNK;    // clamp: loads unconditional

    // mbarrier init (count=1) before anyone can wait on it
    if (tid == 0) {
        uint32_t mb = smem_u32(&s_mbar);
        asm volatile("mbarrier.init.shared.b64 [%0], 1;" :: "r"(mb) : "memory");
    }
    __syncthreads();

    // dtype detection: dist in [1,5]; int64 (LE) => word #1 is high half == 0.
    const bool is64 = (((const int*)distp)[1] == 0);

    // ---- Phase 0: pd + dist loads into registers (overlap proj via PDL) ----
    int idx[2 * LHOPS];
    float scale;
    if (is64) {
        const int4* pp = (const int4*)((const long long*)pdp + (size_t)p * 10);
        #pragma unroll
        for (int j = 0; j < 5; ++j) {
            int4 v = pp[j];              // low words of two int64: .x, .z
            idx[2 * j]     = v.x;
            idx[2 * j + 1] = v.z;
        }
        scale = 0.5f / (float)((const int*)distp)[2 * p];
    } else {
        const int2* pp = (const int2*)((const int*)pdp + (size_t)p * 10);
        #pragma unroll
        for (int j = 0; j < 5; ++j) {
            int2 v = pp[j];
            idx[2 * j]     = v.x;
            idx[2 * j + 1] = v.y;
        }
        scale = 0.5f / (float)((const int*)distp)[p];
    }

#if __CUDA_ARCH__ >= 900
    cudaGridDependencySynchronize();     // g_proj ready (PDL)
#endif

    // ---- Phase 1: one bulk async copy gmem -> smem (41040 B) ----
    if (tid == 0) {
        uint32_t mb  = smem_u32(&s_mbar);
        uint32_t dst = smem_u32(s_tbl);
        unsigned long long src =
            (unsigned long long)__cvta_generic_to_global(g_proj);
        asm volatile(
            "mbarrier.arrive.expect_tx.shared.b64 _, [%0], %1;"
            :: "r"(mb), "r"((uint32_t)TBL_BYTES) : "memory");
        asm volatile(
            "cp.async.bulk.shared::cta.global.mbarrier::complete_tx::bytes "
            "[%0], [%1], %2, [%3];"
            :: "r"(dst), "l"(src), "r"((uint32_t)TBL_BYTES), "r"(mb)
            : "memory");
    }
    // all threads wait on phase 0 of the mbarrier (acquire: orders LDS after)
    {
        uint32_t mb = smem_u32(&s_mbar);
        asm volatile(
            "{\n\t.reg .pred P;\n"
            "W%=:\n\t"
            "mbarrier.try_wait.parity.acquire.cta.shared::cta.b64 P, [%0], 0;\n\t"
            "@!P bra W%=;\n\t}"
            :: "r"(mb) : "memory");
    }

    // ---- Phase 2: gather. Hops 2q,2q+1 share level q: HADD2 pairwise,
    // then fp32 accumulate.
    if (act) {
        float4 al = make_float4(0.f, 0.f, 0.f, 0.f);
        float4 ah = al;
        #pragma unroll
        for (int q = 0; q < LHOPS; ++q) {
            const __half* base = s_tbl + q * NE * HEADS;
            float4 v0 = *(const float4*)(base + idx[2 * q]     * HEADS);
            float4 v1 = *(const float4*)(base + idx[2 * q + 1] * HEADS);
            __half2 s0 = __hadd2(*(__half2*)&v0.x, *(__half2*)&v1.x);
            __half2 s1 = __hadd2(*(__half2*)&v0.y, *(__half2*)&v1.y);
            __half2 s2 = __hadd2(*(__half2*)&v0.z, *(__half2*)&v1.z);
            __half2 s3 = __hadd2(*(__half2*)&v0.w, *(__half2*)&v1.w);
            float2 f0 = __half22float2(s0);
            float2 f1 = __half22float2(s1);
            float2 f2 = __half22float2(s2);
            float2 f3 = __half22float2(s3);
            al.x += f0.x; al.y += f0.y; al.z += f1.x; al.w += f1.y;
            ah.x += f2.x; ah.y += f2.y; ah.z += f3.x; ah.w += f3.y;
        }
        float4* o = (float4*)(out + (size_t)p * HEADS);
        o[0] = make_float4(al.x * scale, al.y * scale, al.z * scale, al.w * scale);
        o[1] = make_float4(ah.x * scale, ah.y * scale, ah.z * scale, ah.w * scale);
    }
}

extern "C" void kernel_launch(void* const* d_in, const int* in_sizes, int n_in,
                              void* d_out, int out_size) {
    const void*  dist = d_in[0];
    const void*  pd   = d_in[1];
    const float* emb  = (const float*)d_in[2];
    const float* w    = (const float*)d_in[3];

    proj_kernel<<<dim3((NE + 31) / 32, LHOPS), 256>>>(emb, w);

    // PDL secondary: may start during proj; griddepsync guards g_proj reads.
    cudaLaunchConfig_t cfg = {};
    cfg.gridDim  = dim3(GRID);
    cfg.blockDim = dim3(1024);
    cfg.dynamicSmemBytes = 0;
    cfg.stream = 0;
    cudaLaunchAttribute attr[1];
    attr[0].id = cudaLaunchAttributeProgrammaticStreamSerialization;
    attr[0].val.programmaticStreamSerializationAllowed = 1;
    cfg.attrs = attr;
    cfg.numAttrs = 1;
    cudaLaunchKernelEx(&cfg, enc_kernel, dist, pd, (float*)d_out);
}